// round 8
// baseline (speedup 1.0000x reference)
#include <cuda_runtime.h>
#include <cuda_fp16.h>
#include <cstdint>

#define NF    16
#define NB    32768
#define NE    64
#define NO    64
#define NH    128
#define NHASH 200000
#define TILE_B 128

// A1 tile: [m=128][k=64] fp16, stride 72 halves (144 B) -> conflict-free ldmatrix
#define S1B 144
#define OFF_A1HI 0              // 18432 B
#define OFF_A1LO 18432          // end 36864
#define SMEM_BYTES 36864

// Pre-split weight fragments in mma.m16n8k16 B-fragment lane layout.
// g_w1frag[((f*4 + ks)*16 + n8)*32 + lane] = {bhi0, bhi1, blo0, blo1}
__device__ __align__(16) uint4 g_w1frag[NF * 4 * 16 * 32];   // 512 KB
__device__ __align__(16) uint4 g_w2frag[NF * 8 * 8 * 32];    // 512 KB
__device__ int g_idx_is64;

__device__ __forceinline__ uint32_t smem_u32(const void* p) {
    uint32_t a;
    asm("{ .reg .u64 t; cvta.to.shared.u64 t, %1; cvt.u32.u64 %0, t; }" : "=r"(a) : "l"(p));
    return a;
}

__device__ __forceinline__ void ldsm_x4(uint32_t* r, uint32_t addr) {
    asm volatile("ldmatrix.sync.aligned.m8n8.x4.shared.b16 {%0,%1,%2,%3}, [%4];"
                 : "=r"(r[0]), "=r"(r[1]), "=r"(r[2]), "=r"(r[3]) : "r"(addr));
}

__device__ __forceinline__ void mma16816(float* d, const uint32_t* a, uint32_t b0, uint32_t b1) {
    asm volatile(
        "mma.sync.aligned.m16n8k16.row.col.f32.f16.f16.f32 "
        "{%0,%1,%2,%3}, {%4,%5,%6,%7}, {%8,%9}, {%0,%1,%2,%3};"
        : "+f"(d[0]), "+f"(d[1]), "+f"(d[2]), "+f"(d[3])
        : "r"(a[0]), "r"(a[1]), "r"(a[2]), "r"(a[3]), "r"(b0), "r"(b1));
}

__device__ __forceinline__ void split_h(float x, __half& hi, __half& lo) {
    hi = __float2half_rn(x);
    lo = __float2half_rn(x - __half2float(hi));
}

__device__ __forceinline__ uint32_t pack2(__half a, __half b) {
    __half2 p = __halves2half2(a, b);
    return *reinterpret_cast<uint32_t*>(&p);
}

// ---------------- prep: idx dtype detect + weight fragment build ----------------
__global__ void prep_kernel(const float* __restrict__ W1,
                            const float* __restrict__ W2,
                            const int*   __restrict__ raw) {
    int g = blockIdx.x * blockDim.x + threadIdx.x;
    if (g == 0) {
        int any = 0;
#pragma unroll
        for (int i = 0; i < 64; i++) any |= raw[2 * i + 1];
        g_idx_is64 = (any == 0) ? 1 : 0;
    }
    if (g < NF * 4 * 16 * 32) {
        const int l  = g & 31;
        const int n8 = (g >> 5) & 15;
        const int ks = (g >> 9) & 3;
        const int f  = g >> 11;
        const int n  = n8 * 8 + (l >> 2);
        const int k0 = ks * 16 + (l & 3) * 2;
        const float* Wf = W1 + (size_t)f * NE * NH;
        float v00 = Wf[(k0 + 0) * NH + n];
        float v01 = Wf[(k0 + 1) * NH + n];
        float v10 = Wf[(k0 + 8) * NH + n];
        float v11 = Wf[(k0 + 9) * NH + n];
        __half h00, l00, h01, l01, h10, l10, h11, l11;
        split_h(v00, h00, l00); split_h(v01, h01, l01);
        split_h(v10, h10, l10); split_h(v11, h11, l11);
        uint4 r;
        r.x = pack2(h00, h01); r.y = pack2(h10, h11);
        r.z = pack2(l00, l01); r.w = pack2(l10, l11);
        g_w1frag[g] = r;
    } else {
        g -= NF * 4 * 16 * 32;
        const int l  = g & 31;
        const int n8 = (g >> 5) & 7;
        const int ks = (g >> 8) & 7;
        const int f  = g >> 11;
        const int n  = n8 * 8 + (l >> 2);
        const int k0 = ks * 16 + (l & 3) * 2;
        const float* Wf = W2 + (size_t)f * NH * NO;
        float v00 = Wf[(k0 + 0) * NO + n];
        float v01 = Wf[(k0 + 1) * NO + n];
        float v10 = Wf[(k0 + 8) * NO + n];
        float v11 = Wf[(k0 + 9) * NO + n];
        __half h00, l00, h01, l01, h10, l10, h11, l11;
        split_h(v00, h00, l00); split_h(v01, h01, l01);
        split_h(v10, h10, l10); split_h(v11, h11, l11);
        uint4 r;
        r.x = pack2(h00, h01); r.y = pack2(h10, h11);
        r.z = pack2(l00, l01); r.w = pack2(l10, l11);
        g_w2frag[g] = r;
    }
}

// ---------------- main kernel ----------------
__global__ __launch_bounds__(256, 2) void sparse_hmma_kernel(
    const int*   __restrict__ inputs_raw,
    const float* __restrict__ tables,
    const float* __restrict__ b1,
    const float* __restrict__ b2,
    float*       __restrict__ out)
{
    extern __shared__ char smem[];
    __shared__ float b1s[NH];
    __shared__ float b2s[NO];

    const uint32_t smem_u = smem_u32(smem);
    const int tid  = threadIdx.x;
    const int wid  = tid >> 5;
    const int lane = tid & 31;
    const int f    = blockIdx.y;
    const int row0 = blockIdx.x * TILE_B;
    const int is64 = g_idx_is64;

    if (tid < NH) b1s[tid] = b1[f * NH + tid];
    if (tid < NO) b2s[tid] = b2[f * NO + tid];

    // ---- gather A1 = emb tile [m=128][k=64] hi/lo, 16B STS ----
    {
        const int m  = tid >> 1;
        const int hf = tid & 1;
        const int flat = (row0 + m) * NF + f;
        const int v = is64 ? inputs_raw[2 * flat] : inputs_raw[flat];
        const int hidx = (v + 1) % NHASH;
        const float4* src =
            (const float4*)(tables + ((size_t)f * NHASH + hidx) * NE + hf * 32);
#pragma unroll
        for (int i = 0; i < 4; i++) {
            float4 va = src[2 * i];
            float4 vb = src[2 * i + 1];
            const int k = hf * 32 + i * 8;
            float vv[8] = {va.x, va.y, va.z, va.w, vb.x, vb.y, vb.z, vb.w};
            __half hi[8], lo[8];
#pragma unroll
            for (int j = 0; j < 8; j++) split_h(vv[j], hi[j], lo[j]);
            uint4 rhi, rlo;
            rhi.x = pack2(hi[0], hi[1]); rhi.y = pack2(hi[2], hi[3]);
            rhi.z = pack2(hi[4], hi[5]); rhi.w = pack2(hi[6], hi[7]);
            rlo.x = pack2(lo[0], lo[1]); rlo.y = pack2(lo[2], lo[3]);
            rlo.z = pack2(lo[4], lo[5]); rlo.w = pack2(lo[6], lo[7]);
            *(uint4*)(smem + OFF_A1HI + m * S1B + k * 2) = rhi;
            *(uint4*)(smem + OFF_A1LO + m * S1B + k * 2) = rlo;
        }
    }
    __syncthreads();

    // ---- GEMM1: each warp computes full H stripe [16m x 128n], 3-pass fp16 ----
    // warp m-tile: rows [wid*16, wid*16+16)
    const uint32_t a_lane1 = (uint32_t)((lane & 15) * S1B + (lane >> 4) * 16);
    const uint32_t abhi1 = smem_u + OFF_A1HI + wid * 16 * S1B + a_lane1;
    const uint32_t ablo1 = smem_u + OFF_A1LO + wid * 16 * S1B + a_lane1;

    float acc1[16][4];
#pragma unroll
    for (int j = 0; j < 16; j++)
#pragma unroll
        for (int q = 0; q < 4; q++) acc1[j][q] = 0.0f;

#pragma unroll
    for (int ks = 0; ks < 4; ks++) {
        uint32_t ah[4], al[4];
        ldsm_x4(ah, abhi1 + ks * 32);
        ldsm_x4(al, ablo1 + ks * 32);
        const uint4* wp = g_w1frag + ((f * 4 + ks) * 16) * 32 + lane;
#pragma unroll
        for (int nt = 0; nt < 16; nt++) {
            uint4 b = wp[nt * 32];
            mma16816(acc1[nt], ah, b.x, b.y);
            mma16816(acc1[nt], al, b.x, b.y);
            mma16816(acc1[nt], ah, b.z, b.w);
        }
    }

    // ---- in-register: H = relu(D1 + b1) -> hi/lo fp16 A-fragments ----
    // C-frag(n-tile nt) == A-frag k-slice: a{0,1} <- nt=2ks (c0c1, c2c3),
    //                                      a{2,3} <- nt=2ks+1.
    uint32_t hh[32], hl[32];    // hh[nt*2+r], r=0: rows(lane>>2), r=1: +8
    {
        const int c0b = 2 * (lane & 3);
#pragma unroll
        for (int nt = 0; nt < 16; nt++) {
            const int c0 = nt * 8 + c0b;
            const float bx = b1s[c0], by = b1s[c0 + 1];
            float v00 = fmaxf(acc1[nt][0] + bx, 0.0f);
            float v01 = fmaxf(acc1[nt][1] + by, 0.0f);
            float v10 = fmaxf(acc1[nt][2] + bx, 0.0f);
            float v11 = fmaxf(acc1[nt][3] + by, 0.0f);
            __half h00, l00, h01, l01, h10, l10, h11, l11;
            split_h(v00, h00, l00); split_h(v01, h01, l01);
            split_h(v10, h10, l10); split_h(v11, h11, l11);
            hh[nt * 2 + 0] = pack2(h00, h01);
            hh[nt * 2 + 1] = pack2(h10, h11);
            hl[nt * 2 + 0] = pack2(l00, l01);
            hl[nt * 2 + 1] = pack2(l10, l11);
        }
    }

    // ---- GEMM2: D2[16m x 64n] = H @ W2^T, A from registers, 3-pass fp16 ----
    float acc2[8][4];
#pragma unroll
    for (int j = 0; j < 8; j++)
#pragma unroll
        for (int q = 0; q < 4; q++) acc2[j][q] = 0.0f;

#pragma unroll
    for (int ks = 0; ks < 8; ks++) {
        uint32_t ah[4] = {hh[4 * ks + 0], hh[4 * ks + 1], hh[4 * ks + 2], hh[4 * ks + 3]};
        uint32_t al[4] = {hl[4 * ks + 0], hl[4 * ks + 1], hl[4 * ks + 2], hl[4 * ks + 3]};
        const uint4* wp = g_w2frag + ((f * 8 + ks) * 8) * 32 + lane;
#pragma unroll
        for (int nt = 0; nt < 8; nt++) {
            uint4 b = wp[nt * 32];
            mma16816(acc2[nt], ah, b.x, b.y);
            mma16816(acc2[nt], al, b.x, b.y);
            mma16816(acc2[nt], ah, b.z, b.w);
        }
    }

    // ---- epilogue: out = D2 + b2, float2 stores ----
    {
        const int gm = row0 + wid * 16 + (lane >> 2);
#pragma unroll
        for (int nt = 0; nt < 8; nt++) {
            const int o = nt * 8 + 2 * (lane & 3);
            const float* a = acc2[nt];
            float2 r0, r1;
            r0.x = a[0] + b2s[o];
            r0.y = a[1] + b2s[o + 1];
            r1.x = a[2] + b2s[o];
            r1.y = a[3] + b2s[o + 1];
            *(float2*)(out + ((size_t)f * NB + gm) * NO + o) = r0;
            *(float2*)(out + ((size_t)f * NB + gm + 8) * NO + o) = r1;
        }
    }
}

extern "C" void kernel_launch(void* const* d_in, const int* in_sizes, int n_in,
                              void* d_out, int out_size) {
    const int*   inputs_raw = (const int*)d_in[0];
    const float* tables     = (const float*)d_in[1];
    const float* W1         = (const float*)d_in[2];
    const float* b1         = (const float*)d_in[3];
    const float* W2         = (const float*)d_in[4];
    const float* b2         = (const float*)d_in[5];
    float*       out        = (float*)d_out;

    cudaFuncSetAttribute(sparse_hmma_kernel,
                         cudaFuncAttributeMaxDynamicSharedMemorySize, SMEM_BYTES);

    prep_kernel<<<256, 256>>>(W1, W2, inputs_raw);

    dim3 grid(NB / TILE_B, NF);
    sparse_hmma_kernel<<<grid, 256, SMEM_BYTES>>>(inputs_raw, tables, b1, b2, out);
}